// round 4
// baseline (speedup 1.0000x reference)
#include <cuda_runtime.h>
#include <cuda_bf16.h>
#include <stdint.h>

#define N_NODES 50000
#define N_EDGES 800000
#define DIM 128
#define VDIM 32            // DIM/4 float4 per row
#define OUT_DIM 2
#define LEAKY 0.01f
#define LN_EPS 1e-5f

// ---------------- scratch (device globals; allocation is forbidden) ----------------
__device__ int    g_deg_in[N_NODES];
__device__ int    g_deg_out[N_NODES];
__device__ float  g_norm_in[N_NODES];
__device__ float  g_norm_out[N_NODES];
__device__ int    g_row_start[N_NODES + 1];
__device__ int    g_fill[N_NODES];
__device__ int    g_col[N_EDGES];

__device__ float4 g_agg[(size_t)N_NODES * VDIM];   // aggregation output
__device__ float4 g_y[(size_t)N_NODES * VDIM];     // gemm output
__device__ float4 g_x[(size_t)N_NODES * VDIM];     // post LN+leaky features
__device__ float2 g_proj[N_NODES];

__device__ __forceinline__ int clamp_idx(int v) {
    v = v < 0 ? 0 : v;
    return v >= N_NODES ? N_NODES - 1 : v;
}

// ---------------- setup kernels ----------------
__global__ void zero_deg_kernel() {
    int i = blockIdx.x * blockDim.x + threadIdx.x;
    if (i < N_NODES) { g_deg_in[i] = 0; g_deg_out[i] = 0; }
}

__global__ void count_deg_kernel(const int* __restrict__ src,
                                 const int* __restrict__ dst) {
    int e = blockIdx.x * blockDim.x + threadIdx.x;
    if (e >= N_EDGES) return;
    atomicAdd(&g_deg_out[clamp_idx(src[e])], 1);
    atomicAdd(&g_deg_in[clamp_idx(dst[e])], 1);
}

__global__ void norm_kernel() {
    int i = blockIdx.x * blockDim.x + threadIdx.x;
    if (i >= N_NODES) return;
    g_norm_out[i] = rsqrtf(fmaxf((float)g_deg_out[i], 1.0f));
    g_norm_in[i]  = rsqrtf(fmaxf((float)g_deg_in[i], 1.0f));
}

// single-block exclusive scan of g_deg_in -> g_row_start
__global__ void scan_kernel() {
    __shared__ int sh[1024];
    __shared__ int carry_sh;
    int tid = threadIdx.x;
    if (tid == 0) carry_sh = 0;
    __syncthreads();
    for (int base = 0; base < N_NODES; base += 1024) {
        int i = base + tid;
        int v = (i < N_NODES) ? g_deg_in[i] : 0;
        sh[tid] = v;
        __syncthreads();
        for (int off = 1; off < 1024; off <<= 1) {
            int t = (tid >= off) ? sh[tid - off] : 0;
            __syncthreads();
            sh[tid] += t;
            __syncthreads();
        }
        int incl  = sh[tid];
        int carry = carry_sh;
        if (i < N_NODES) g_row_start[i] = carry + incl - v;
        __syncthreads();
        if (tid == 1023) carry_sh = carry + incl;
        __syncthreads();
    }
    if (tid == 0) g_row_start[N_NODES] = carry_sh;
}

__global__ void copy_fill_kernel() {
    int i = blockIdx.x * blockDim.x + threadIdx.x;
    if (i < N_NODES) g_fill[i] = g_row_start[i];
}

__global__ void fill_csr_kernel(const int* __restrict__ src,
                                const int* __restrict__ dst) {
    int e = blockIdx.x * blockDim.x + threadIdx.x;
    if (e >= N_EDGES) return;
    int d = clamp_idx(dst[e]);
    int pos = atomicAdd(&g_fill[d], 1);
    g_col[pos] = clamp_idx(src[e]);
}

// ---------------- aggregation: warp per node, 128 feats as float4/lane ----------------
// USE_GX=false: read `feat` param; USE_GX=true: read g_x. Output: g_agg.
template <bool USE_GX>
__global__ __launch_bounds__(256)
void agg128_kernel(const float* __restrict__ feat) {
    int node = blockIdx.x * (blockDim.x >> 5) + (threadIdx.x >> 5);
    if (node >= N_NODES) return;
    int lane = threadIdx.x & 31;
    int beg = g_row_start[node];
    int end = g_row_start[node + 1];
    float ax = 0.f, ay = 0.f, az = 0.f, aw = 0.f;
    for (int e = beg; e < end; e++) {
        int c = g_col[e];
        float w = g_norm_out[c];
        float4 v;
        if (USE_GX) v = g_x[(size_t)c * VDIM + lane];
        else        v = ((const float4*)(feat + (size_t)c * DIM))[lane];
        ax = fmaf(w, v.x, ax);
        ay = fmaf(w, v.y, ay);
        az = fmaf(w, v.z, az);
        aw = fmaf(w, v.w, aw);
    }
    float ni = g_norm_in[node];
    float4 o = { ax * ni, ay * ni, az * ni, aw * ni };
    g_agg[(size_t)node * VDIM + lane] = o;
}

// ---------------- GEMM: g_y[N,128] = g_agg[N,128] @ W[128,128] + b ----------------
#define GTM 64
#define GTK 32
__global__ __launch_bounds__(256)
void gemm_bias_kernel(const float* __restrict__ W, const float* __restrict__ b) {
    __shared__ float As[GTM][GTK + 1];
    __shared__ float Bs[GTK][DIM + 4];
    int tid = threadIdx.x;
    int rowBase = blockIdx.x * GTM;
    int tx = tid & 15;   // 16 col-groups of 8
    int ty = tid >> 4;   // 16 row-groups of 4
    float acc[4][8];
#pragma unroll
    for (int i = 0; i < 4; i++)
#pragma unroll
        for (int j = 0; j < 8; j++) acc[i][j] = 0.f;

    const float* Af = (const float*)g_agg;
    for (int kk = 0; kk < DIM; kk += GTK) {
#pragma unroll
        for (int i = 0; i < 8; i++) {        // 64x32 A tile: 2048 = 8*256
            int l = tid + i * 256;
            int r = l >> 5, c = l & 31;
            int gr = rowBase + r;
            As[r][c] = (gr < N_NODES) ? Af[(size_t)gr * DIM + kk + c] : 0.f;
        }
#pragma unroll
        for (int i = 0; i < 16; i++) {       // 32x128 W tile: 4096 = 16*256  (FIXED)
            int l = tid + i * 256;
            int r = l >> 7, c = l & 127;
            Bs[r][c] = W[(size_t)(kk + r) * DIM + c];
        }
        __syncthreads();
#pragma unroll
        for (int k = 0; k < GTK; k++) {
            float av[4], bv[8];
#pragma unroll
            for (int i = 0; i < 4; i++) av[i] = As[ty * 4 + i][k];
#pragma unroll
            for (int j = 0; j < 8; j++) bv[j] = Bs[k][tx * 8 + j];
#pragma unroll
            for (int i = 0; i < 4; i++)
#pragma unroll
                for (int j = 0; j < 8; j++) acc[i][j] = fmaf(av[i], bv[j], acc[i][j]);
        }
        __syncthreads();
    }
#pragma unroll
    for (int i = 0; i < 4; i++) {
        int gr = rowBase + ty * 4 + i;
        if (gr < N_NODES) {
            int col = tx * 8;
            float4 o0, o1;
            o0.x = acc[i][0] + b[col + 0];
            o0.y = acc[i][1] + b[col + 1];
            o0.z = acc[i][2] + b[col + 2];
            o0.w = acc[i][3] + b[col + 3];
            o1.x = acc[i][4] + b[col + 4];
            o1.y = acc[i][5] + b[col + 5];
            o1.z = acc[i][6] + b[col + 6];
            o1.w = acc[i][7] + b[col + 7];
            g_y[(size_t)gr * VDIM + (col >> 2)]     = o0;
            g_y[(size_t)gr * VDIM + (col >> 2) + 1] = o1;
        }
    }
}

// ---------------- LayerNorm + LeakyReLU: warp per row (g_y -> g_x) ----------------
__global__ __launch_bounds__(256)
void ln_leaky_kernel(const float* __restrict__ g, const float* __restrict__ be) {
    int row = blockIdx.x * (blockDim.x >> 5) + (threadIdx.x >> 5);
    if (row >= N_NODES) return;
    int lane = threadIdx.x & 31;
    float4 v = g_y[(size_t)row * VDIM + lane];
    float s = v.x + v.y + v.z + v.w;
#pragma unroll
    for (int o = 16; o; o >>= 1) s += __shfl_xor_sync(0xffffffffu, s, o);
    float mu = s * (1.f / DIM);
    float dx = v.x - mu, dy = v.y - mu, dz = v.z - mu, dw = v.w - mu;
    float q = dx * dx + dy * dy + dz * dz + dw * dw;
#pragma unroll
    for (int o = 16; o; o >>= 1) q += __shfl_xor_sync(0xffffffffu, q, o);
    float rstd = rsqrtf(q * (1.f / DIM) + LN_EPS);
    float4 gg = ((const float4*)g)[lane];
    float4 bb = ((const float4*)be)[lane];
    float4 o;
    o.x = dx * rstd * gg.x + bb.x;
    o.y = dy * rstd * gg.y + bb.y;
    o.z = dz * rstd * gg.z + bb.z;
    o.w = dw * rstd * gg.w + bb.w;
    o.x = o.x > 0.f ? o.x : LEAKY * o.x;
    o.y = o.y > 0.f ? o.y : LEAKY * o.y;
    o.z = o.z > 0.f ? o.z : LEAKY * o.z;
    o.w = o.w > 0.f ? o.w : LEAKY * o.w;
    g_x[(size_t)row * VDIM + lane] = o;
}

// ---------------- layer-3: project first (W3 folded before aggregation) ----------------
__global__ __launch_bounds__(256)
void proj2_kernel(const float* __restrict__ W3) {
    int node = blockIdx.x * (blockDim.x >> 5) + (threadIdx.x >> 5);
    if (node >= N_NODES) return;
    int lane = threadIdx.x & 31;
    float no = g_norm_out[node];
    float4 v = g_x[(size_t)node * VDIM + lane];
    int k = lane * 4;
    float s0 = v.x * W3[k * 2 + 0] + v.y * W3[k * 2 + 2] + v.z * W3[k * 2 + 4] + v.w * W3[k * 2 + 6];
    float s1 = v.x * W3[k * 2 + 1] + v.y * W3[k * 2 + 3] + v.z * W3[k * 2 + 5] + v.w * W3[k * 2 + 7];
#pragma unroll
    for (int o = 16; o; o >>= 1) {
        s0 += __shfl_xor_sync(0xffffffffu, s0, o);
        s1 += __shfl_xor_sync(0xffffffffu, s1, o);
    }
    if (lane == 0) {
        float2 p = { no * s0, no * s1 };
        g_proj[node] = p;
    }
}

__global__ void agg2_kernel(const float* __restrict__ b3, float* __restrict__ out) {
    int node = blockIdx.x * blockDim.x + threadIdx.x;
    if (node >= N_NODES) return;
    int beg = g_row_start[node];
    int end = g_row_start[node + 1];
    float a0 = 0.f, a1 = 0.f;
    for (int e = beg; e < end; e++) {
        float2 p = g_proj[g_col[e]];
        a0 += p.x;
        a1 += p.y;
    }
    float ni = g_norm_in[node];
    out[node * 2 + 0] = ni * a0 + b3[0];
    out[node * 2 + 1] = ni * a1 + b3[1];
}

// ---------------- launch: pure kernel launches, no runtime API ----------------
extern "C" void kernel_launch(void* const* d_in, const int* in_sizes, int n_in,
                              void* d_out, int out_size) {
    const float* feat = (const float*)d_in[0];
    const int*   src  = (const int*)d_in[1];   // int32 (JAX x64 disabled)
    const int*   dst  = (const int*)d_in[2];
    const float* W1  = (const float*)d_in[3];
    const float* b1  = (const float*)d_in[4];
    const float* W2  = (const float*)d_in[5];
    const float* b2  = (const float*)d_in[6];
    const float* W3  = (const float*)d_in[7];
    const float* b3  = (const float*)d_in[8];
    const float* g1  = (const float*)d_in[9];
    const float* be1 = (const float*)d_in[10];
    const float* g2  = (const float*)d_in[11];
    const float* be2 = (const float*)d_in[12];
    float* out = (float*)d_out;

    const int NB_N = (N_NODES + 255) / 256;
    const int NB_E = (N_EDGES + 255) / 256;
    const int NB_W = (N_NODES + 7) / 8;     // warp-per-node, 8 warps/block
    const int NB_G = (N_NODES + GTM - 1) / GTM;

    // graph structure (per launch, deterministic)
    zero_deg_kernel<<<NB_N, 256>>>();
    count_deg_kernel<<<NB_E, 256>>>(src, dst);
    norm_kernel<<<NB_N, 256>>>();
    scan_kernel<<<1, 1024>>>();
    copy_fill_kernel<<<NB_N, 256>>>();
    fill_csr_kernel<<<NB_E, 256>>>(src, dst);

    // layer 1
    agg128_kernel<false><<<NB_W, 256>>>(feat);
    gemm_bias_kernel<<<NB_G, 256>>>(W1, b1);
    ln_leaky_kernel<<<NB_W, 256>>>(g1, be1);

    // layer 2
    agg128_kernel<true><<<NB_W, 256>>>(feat);
    gemm_bias_kernel<<<NB_G, 256>>>(W2, b2);
    ln_leaky_kernel<<<NB_W, 256>>>(g2, be2);

    // layer 3 (W3 folded before aggregation: 64x less edge traffic)
    proj2_kernel<<<NB_W, 256>>>(W3);
    agg2_kernel<<<NB_N, 256>>>(b3, out);
}

// round 5
// speedup vs baseline: 1.3850x; 1.3850x over previous
#include <cuda_runtime.h>
#include <cuda_bf16.h>
#include <stdint.h>

#define N_NODES 50000
#define N_EDGES 800000
#define DIM 128
#define VDIM 32            // DIM/4 float4 per row
#define LEAKY 0.01f
#define LN_EPS 1e-5f

#define SCAN_BLK 256
#define N_SBLK ((N_NODES + SCAN_BLK - 1) / SCAN_BLK)   // 196

// ---------------- scratch (device globals; allocation is forbidden) ----------------
__device__ int    g_deg_in[N_NODES];
__device__ int    g_deg_out[N_NODES];
__device__ float  g_norm_in[N_NODES];
__device__ float  g_norm_out[N_NODES];
__device__ int    g_row_start[N_NODES + 1];
__device__ int    g_fill[N_NODES];
__device__ int    g_col[N_EDGES];
__device__ int    g_bsum[N_SBLK];

__device__ float4 g_agg[(size_t)N_NODES * VDIM];   // aggregation output
__device__ float4 g_x[(size_t)N_NODES * VDIM];     // post LN+leaky features (layer 1)
__device__ float2 g_proj[N_NODES];                 // layer-3 projected features

__device__ __forceinline__ int clamp_idx(int v) {
    v = v < 0 ? 0 : v;
    return v >= N_NODES ? N_NODES - 1 : v;
}

// ---------------- setup ----------------
__global__ void zero_deg_kernel() {
    int i = blockIdx.x * blockDim.x + threadIdx.x;
    if (i < N_NODES) { g_deg_in[i] = 0; g_deg_out[i] = 0; }
}

__global__ void count_deg_kernel(const int* __restrict__ src,
                                 const int* __restrict__ dst) {
    int e = blockIdx.x * blockDim.x + threadIdx.x;
    if (e >= N_EDGES) return;
    atomicAdd(&g_deg_out[clamp_idx(src[e])], 1);
    atomicAdd(&g_deg_in[clamp_idx(dst[e])], 1);
}

// phase A: per-block sums of deg_in
__global__ __launch_bounds__(SCAN_BLK)
void scan_bsum_kernel() {
    int i = blockIdx.x * SCAN_BLK + threadIdx.x;
    int v = (i < N_NODES) ? g_deg_in[i] : 0;
#pragma unroll
    for (int o = 16; o; o >>= 1) v += __shfl_xor_sync(0xffffffffu, v, o);
    __shared__ int wsum[SCAN_BLK / 32];
    if ((threadIdx.x & 31) == 0) wsum[threadIdx.x >> 5] = v;
    __syncthreads();
    if (threadIdx.x == 0) {
        int s = 0;
#pragma unroll
        for (int w = 0; w < SCAN_BLK / 32; w++) s += wsum[w];
        g_bsum[blockIdx.x] = s;
    }
}

// phase B: one-block exclusive scan of the 196 partials
__global__ __launch_bounds__(256)
void scan_partials_kernel() {
    __shared__ int sh[256];
    int tid = threadIdx.x;
    int v = (tid < N_SBLK) ? g_bsum[tid] : 0;
    sh[tid] = v;
    __syncthreads();
#pragma unroll
    for (int off = 1; off < 256; off <<= 1) {
        int t = (tid >= off) ? sh[tid - off] : 0;
        __syncthreads();
        sh[tid] += t;
        __syncthreads();
    }
    if (tid < N_SBLK) g_bsum[tid] = sh[tid] - v;          // exclusive prefix
    if (tid == 255) g_row_start[N_NODES] = sh[255];       // total edge count
}

// phase C: per-block rescan + global offset; also fill pointers and degree norms
__global__ __launch_bounds__(SCAN_BLK)
void scan_final_kernel() {
    int tid = threadIdx.x;
    int i = blockIdx.x * SCAN_BLK + tid;
    int lane = tid & 31, wid = tid >> 5;
    int v = (i < N_NODES) ? g_deg_in[i] : 0;
    int incl = v;
#pragma unroll
    for (int o = 1; o < 32; o <<= 1) {
        int t = __shfl_up_sync(0xffffffffu, incl, o);
        if (lane >= o) incl += t;
    }
    __shared__ int wsum[SCAN_BLK / 32];
    __shared__ int woff[SCAN_BLK / 32];
    if (lane == 31) wsum[wid] = incl;
    __syncthreads();
    if (tid == 0) {
        int s = 0;
#pragma unroll
        for (int w = 0; w < SCAN_BLK / 32; w++) { woff[w] = s; s += wsum[w]; }
    }
    __syncthreads();
    if (i < N_NODES) {
        int excl = incl - v + woff[wid] + g_bsum[blockIdx.x];
        g_row_start[i] = excl;
        g_fill[i] = excl;
        g_norm_out[i] = rsqrtf(fmaxf((float)g_deg_out[i], 1.0f));
        g_norm_in[i]  = rsqrtf(fmaxf((float)v, 1.0f));
    }
}

__global__ void fill_csr_kernel(const int* __restrict__ src,
                                const int* __restrict__ dst) {
    int e = blockIdx.x * blockDim.x + threadIdx.x;
    if (e >= N_EDGES) return;
    int d = clamp_idx(dst[e]);
    int pos = atomicAdd(&g_fill[d], 1);
    g_col[pos] = clamp_idx(src[e]);
}

// ---------------- aggregation: warp per node, 128 feats as float4/lane ----------------
template <bool USE_GX>
__global__ __launch_bounds__(256)
void agg128_kernel(const float* __restrict__ feat) {
    int node = blockIdx.x * (blockDim.x >> 5) + (threadIdx.x >> 5);
    if (node >= N_NODES) return;
    int lane = threadIdx.x & 31;
    int beg = g_row_start[node];
    int end = g_row_start[node + 1];
    float ax = 0.f, ay = 0.f, az = 0.f, aw = 0.f;
    for (int e = beg; e < end; e++) {
        int c = g_col[e];
        float w = g_norm_out[c];
        float4 v;
        if (USE_GX) v = g_x[(size_t)c * VDIM + lane];
        else        v = ((const float4*)(feat + (size_t)c * DIM))[lane];
        ax = fmaf(w, v.x, ax);
        ay = fmaf(w, v.y, ay);
        az = fmaf(w, v.z, az);
        aw = fmaf(w, v.w, aw);
    }
    float ni = g_norm_in[node];
    float4 o = { ax * ni, ay * ni, az * ni, aw * ni };
    g_agg[(size_t)node * VDIM + lane] = o;
}

// ---------------- fused GEMM + bias + LayerNorm + LeakyReLU (+ optional W3 projection) ----
// MODE 0: write normalized activations to g_x.
// MODE 1: additionally project onto W3 (128x2) with norm_out scaling -> g_proj (skip g_x).
#define GTM 64
#define GTK 32
template <int MODE>
__global__ __launch_bounds__(256)
void gemm_ln_kernel(const float* __restrict__ W, const float* __restrict__ b,
                    const float* __restrict__ g, const float* __restrict__ be,
                    const float* __restrict__ W3) {
    __shared__ float As[GTM][GTK + 1];
    __shared__ float Bs[GTK][DIM + 4];
    int tid = threadIdx.x;
    int rowBase = blockIdx.x * GTM;
    int tx = tid & 15;   // 16 col-groups of 8
    int ty = tid >> 4;   // 16 row-groups of 4
    float acc[4][8];
#pragma unroll
    for (int i = 0; i < 4; i++)
#pragma unroll
        for (int j = 0; j < 8; j++) acc[i][j] = 0.f;

    const float* Af = (const float*)g_agg;
    for (int kk = 0; kk < DIM; kk += GTK) {
#pragma unroll
        for (int i = 0; i < 8; i++) {        // 64x32 A tile
            int l = tid + i * 256;
            int r = l >> 5, c = l & 31;
            int gr = rowBase + r;
            As[r][c] = (gr < N_NODES) ? Af[(size_t)gr * DIM + kk + c] : 0.f;
        }
#pragma unroll
        for (int i = 0; i < 16; i++) {       // 32x128 W tile
            int l = tid + i * 256;
            int r = l >> 7, c = l & 127;
            Bs[r][c] = W[(size_t)(kk + r) * DIM + c];
        }
        __syncthreads();
#pragma unroll
        for (int k = 0; k < GTK; k++) {
            float av[4], bv[8];
#pragma unroll
            for (int i = 0; i < 4; i++) av[i] = As[ty * 4 + i][k];
#pragma unroll
            for (int j = 0; j < 8; j++) bv[j] = Bs[k][tx * 8 + j];
#pragma unroll
            for (int i = 0; i < 4; i++)
#pragma unroll
                for (int j = 0; j < 8; j++) acc[i][j] = fmaf(av[i], bv[j], acc[i][j]);
        }
        __syncthreads();
    }

    // epilogue: bias + LayerNorm + leaky (+ optional projection), all in registers
    int col = tx * 8;
    float bias[8], gg[8], bb[8];
#pragma unroll
    for (int j = 0; j < 8; j++) { bias[j] = b[col + j]; gg[j] = g[col + j]; bb[j] = be[col + j]; }

#pragma unroll
    for (int i = 0; i < 4; i++) {
        int gr = rowBase + ty * 4 + i;
#pragma unroll
        for (int j = 0; j < 8; j++) acc[i][j] += bias[j];
        // mean across 128 cols: 16 lanes (same 16-lane half-warp share a row group)
        float s = 0.f;
#pragma unroll
        for (int j = 0; j < 8; j++) s += acc[i][j];
#pragma unroll
        for (int o = 8; o; o >>= 1) s += __shfl_xor_sync(0xffffffffu, s, o);
        float mu = s * (1.f / DIM);
        float q = 0.f;
#pragma unroll
        for (int j = 0; j < 8; j++) { float d = acc[i][j] - mu; q += d * d; }
#pragma unroll
        for (int o = 8; o; o >>= 1) q += __shfl_xor_sync(0xffffffffu, q, o);
        float rstd = rsqrtf(q * (1.f / DIM) + LN_EPS);
        float val[8];
#pragma unroll
        for (int j = 0; j < 8; j++) {
            float t = (acc[i][j] - mu) * rstd * gg[j] + bb[j];
            val[j] = t > 0.f ? t : LEAKY * t;
        }
        if (MODE == 0) {
            if (gr < N_NODES) {
                float4 o0 = { val[0], val[1], val[2], val[3] };
                float4 o1 = { val[4], val[5], val[6], val[7] };
                g_x[(size_t)gr * VDIM + (col >> 2)]     = o0;
                g_x[(size_t)gr * VDIM + (col >> 2) + 1] = o1;
            }
        } else {
            float s0 = 0.f, s1 = 0.f;
#pragma unroll
            for (int j = 0; j < 8; j++) {
                s0 = fmaf(val[j], W3[(col + j) * 2 + 0], s0);
                s1 = fmaf(val[j], W3[(col + j) * 2 + 1], s1);
            }
#pragma unroll
            for (int o = 8; o; o >>= 1) {
                s0 += __shfl_xor_sync(0xffffffffu, s0, o);
                s1 += __shfl_xor_sync(0xffffffffu, s1, o);
            }
            if (tx == 0 && gr < N_NODES) {
                float no = g_norm_out[gr];
                float2 p = { no * s0, no * s1 };
                g_proj[gr] = p;
            }
        }
    }
}

// ---------------- final aggregation over 2-dim projected features ----------------
__global__ void agg2_kernel(const float* __restrict__ b3, float* __restrict__ out) {
    int node = blockIdx.x * blockDim.x + threadIdx.x;
    if (node >= N_NODES) return;
    int beg = g_row_start[node];
    int end = g_row_start[node + 1];
    float a0 = 0.f, a1 = 0.f;
    for (int e = beg; e < end; e++) {
        float2 p = g_proj[g_col[e]];
        a0 += p.x;
        a1 += p.y;
    }
    float ni = g_norm_in[node];
    out[node * 2 + 0] = ni * a0 + b3[0];
    out[node * 2 + 1] = ni * a1 + b3[1];
}

// ---------------- launch: pure kernel launches, no runtime API ----------------
extern "C" void kernel_launch(void* const* d_in, const int* in_sizes, int n_in,
                              void* d_out, int out_size) {
    const float* feat = (const float*)d_in[0];
    const int*   src  = (const int*)d_in[1];   // int32 (JAX x64 disabled)
    const int*   dst  = (const int*)d_in[2];
    const float* W1  = (const float*)d_in[3];
    const float* b1  = (const float*)d_in[4];
    const float* W2  = (const float*)d_in[5];
    const float* b2  = (const float*)d_in[6];
    const float* W3  = (const float*)d_in[7];
    const float* b3  = (const float*)d_in[8];
    const float* g1  = (const float*)d_in[9];
    const float* be1 = (const float*)d_in[10];
    const float* g2  = (const float*)d_in[11];
    const float* be2 = (const float*)d_in[12];
    float* out = (float*)d_out;

    const int NB_N = (N_NODES + 255) / 256;
    const int NB_E = (N_EDGES + 255) / 256;
    const int NB_W = (N_NODES + 7) / 8;     // warp-per-node, 8 warps/block
    const int NB_G = (N_NODES + GTM - 1) / GTM;

    // graph structure
    zero_deg_kernel<<<NB_N, 256>>>();
    count_deg_kernel<<<NB_E, 256>>>(src, dst);
    scan_bsum_kernel<<<N_SBLK, SCAN_BLK>>>();
    scan_partials_kernel<<<1, 256>>>();
    scan_final_kernel<<<N_SBLK, SCAN_BLK>>>();   // also norms + fill ptrs
    fill_csr_kernel<<<NB_E, 256>>>(src, dst);

    // layer 1: agg -> fused gemm+bias+LN+leaky -> g_x
    agg128_kernel<false><<<NB_W, 256>>>(feat);
    gemm_ln_kernel<0><<<NB_G, 256>>>(W1, b1, g1, be1, nullptr);

    // layer 2: agg -> fused gemm+bias+LN+leaky+W3 projection -> g_proj
    agg128_kernel<true><<<NB_W, 256>>>(feat);
    gemm_ln_kernel<1><<<NB_G, 256>>>(W2, b2, g2, be2, W3);

    // layer 3 aggregation over 2-dim projections
    agg2_kernel<<<NB_N, 256>>>(b3, out);
}